// round 1
// baseline (speedup 1.0000x reference)
#include <cuda_runtime.h>
#include <math.h>

// Problem shape (fixed by the dataset)
#define S_TOT 4096
#define C_TOT 64
#define F_TOT 256

// ---------------- scratch (device globals: no allocation allowed) ----------
__device__ float    g_norm[S_TOT * F_TOT];   // normalized rays r[s][f]
__device__ float    g_len [S_TOT];           // ray lengths
__device__ unsigned g_mu  [S_TOT];           // min over c of mu_pos, as float bits
__device__ float    g_v   [C_TOT * F_TOT];   // v_c = P_c t + q_c
__device__ float    g_cst [C_TOT];           // q·t + 0.5 tPt - b

// ---------------- kernel 1: normalize rays, init mu ------------------------
// 1 warp per sample, 8 samples per 256-thread CTA
__global__ void k_norm(const float* __restrict__ zs,
                       const float* __restrict__ point)
{
    int warp = threadIdx.x >> 5;
    int lane = threadIdx.x & 31;
    int s = blockIdx.x * 8 + warp;

    const float4* z4 = (const float4*)(zs + (size_t)s * F_TOT);
    const float4* p4 = (const float4*)point;

    float4 a = z4[lane];
    float4 b = z4[lane + 32];
    float4 pa = p4[lane];
    float4 pb = p4[lane + 32];

    a.x -= pa.x; a.y -= pa.y; a.z -= pa.z; a.w -= pa.w;
    b.x -= pb.x; b.y -= pb.y; b.z -= pb.z; b.w -= pb.w;

    float ss = a.x*a.x + a.y*a.y + a.z*a.z + a.w*a.w
             + b.x*b.x + b.y*b.y + b.z*b.z + b.w*b.w;

    #pragma unroll
    for (int off = 16; off; off >>= 1)
        ss += __shfl_xor_sync(0xffffffffu, ss, off);

    float len = fmaxf(sqrtf(ss), 1e-12f);
    float inv = 1.0f / len;

    a.x *= inv; a.y *= inv; a.z *= inv; a.w *= inv;
    b.x *= inv; b.y *= inv; b.z *= inv; b.w *= inv;

    float4* o4 = (float4*)(g_norm + (size_t)s * F_TOT);
    o4[lane]      = a;
    o4[lane + 32] = b;

    if (lane == 0) {
        g_len[s] = len;
        g_mu[s]  = 0x7f800000u;   // +inf
    }
}

// ---------------- kernel 0: per-constraint precompute -----------------------
// v_c[k] = sum_f P[c,k,f] t[f] + q[c,k]  (P symmetric => read column-coalesced)
// cst_c  = q_c·t + 0.5 * tPt - b_c
__global__ void k_pre(const float* __restrict__ P,
                      const float* __restrict__ q,
                      const float* __restrict__ b,
                      const float* __restrict__ point)
{
    int c = blockIdx.x;
    int k = threadIdx.x;

    __shared__ float t_sm[F_TOT];
    __shared__ float red1[F_TOT];
    __shared__ float red2[F_TOT];

    t_sm[k] = point[k];
    __syncthreads();

    const float* Pc = P + (size_t)c * F_TOT * F_TOT;
    float v = 0.0f;
    // (P t)[k] = sum_f P[c,f,k] * t[f]   (symmetry: P[c,f,k] == P[c,k,f])
    for (int f = 0; f < F_TOT; f++)
        v += Pc[f * F_TOT + k] * t_sm[f];

    float qk = q[c * F_TOT + k];
    float tk = t_sm[k];

    red1[k] = v  * tk;   // -> tPt
    red2[k] = qk * tk;   // -> q·t
    __syncthreads();
    for (int off = 128; off; off >>= 1) {
        if (k < off) { red1[k] += red1[k + off]; red2[k] += red2[k + off]; }
        __syncthreads();
    }

    g_v[c * F_TOT + k] = v + qk;
    if (k == 0)
        g_cst[c] = red2[0] + 0.5f * red1[0] - b[c];
}

// ---------------- kernel 2: fused quadratic form + mu + min-reduce ----------
// Grid (S/64, C). Each CTA: 64 samples x 1 constraint.
// smem layout (dynamic):
//   Rt  [256][65]  transposed r block (pad 65 -> conflict-free both ways)
//   Ps  [32][64]   P k-tile x f-tile
//   vsm [256]      v_c
//   red [2][64][16] cross-thread partial sums (rPr, r·v)
#define SBP 65
__global__ void __launch_bounds__(256, 2) k_main(const float* __restrict__ P)
{
    extern __shared__ float smem[];
    float* Rt  = smem;                   // 256*65
    float* Ps  = Rt + 256 * SBP;         // 32*64
    float* vsm = Ps + 32 * 64;           // 256
    float* red = vsm + 256;              // 2048

    int t  = threadIdx.x;
    int s0 = blockIdx.x * 64;
    int c  = blockIdx.y;

    // load R block transposed: Rt[k][s] = r[s0+s][k]
    for (int idx = t; idx < 64 * 256; idx += 256) {
        int s = idx >> 8;
        int k = idx & 255;
        Rt[k * SBP + s] = g_norm[(size_t)(s0 + s) * F_TOT + k];
    }
    vsm[t] = g_v[c * F_TOT + t];
    __syncthreads();

    int tx = t & 15;   // f-group (4 cols each)
    int ty = t >> 4;   // s-group (4 rows each)

    float accP[4] = {0.f, 0.f, 0.f, 0.f};
    float accV[4] = {0.f, 0.f, 0.f, 0.f};

    const float* Pc = P + (size_t)c * F_TOT * F_TOT;

    for (int f0 = 0; f0 < 256; f0 += 64) {
        float u[4][4];
        #pragma unroll
        for (int i = 0; i < 4; i++)
            #pragma unroll
            for (int j = 0; j < 4; j++)
                u[i][j] = 0.0f;

        for (int k0 = 0; k0 < 256; k0 += 32) {
            __syncthreads();
            // load P tile: P[c, k0+kk, f0..f0+63], 512 float4 by 256 threads
            #pragma unroll
            for (int i = 0; i < 2; i++) {
                int vi  = t + i * 256;
                int kk  = vi >> 4;
                int ffq = vi & 15;
                ((float4*)(Ps + kk * 64))[ffq] =
                    ((const float4*)(Pc + (k0 + kk) * 256 + f0))[ffq];
            }
            __syncthreads();

            #pragma unroll 8
            for (int kk = 0; kk < 32; kk++) {
                const float* rrow = Rt + (k0 + kk) * SBP + ty * 4;
                float a0 = rrow[0];
                float a1 = rrow[1];
                float a2 = rrow[2];
                float a3 = rrow[3];
                float4 b4 = *(const float4*)(Ps + kk * 64 + tx * 4);

                u[0][0] += a0 * b4.x; u[0][1] += a0 * b4.y; u[0][2] += a0 * b4.z; u[0][3] += a0 * b4.w;
                u[1][0] += a1 * b4.x; u[1][1] += a1 * b4.y; u[1][2] += a1 * b4.z; u[1][3] += a1 * b4.w;
                u[2][0] += a2 * b4.x; u[2][1] += a2 * b4.y; u[2][2] += a2 * b4.z; u[2][3] += a2 * b4.w;
                u[3][0] += a3 * b4.x; u[3][1] += a3 * b4.y; u[3][2] += a3 * b4.z; u[3][3] += a3 * b4.w;
            }
        }

        // epilogue for this f-tile: fold u into rPr partials, and r·v partials
        #pragma unroll
        for (int j = 0; j < 4; j++) {
            int f = f0 + tx * 4 + j;
            float vj = vsm[f];
            #pragma unroll
            for (int i = 0; i < 4; i++) {
                float r = Rt[f * SBP + ty * 4 + i];
                accP[i] += u[i][j] * r;
                accV[i] += vj * r;
            }
        }
    }

    // cross-thread reduction over tx (16 f-groups) per sample
    #pragma unroll
    for (int i = 0; i < 4; i++) {
        int s = ty * 4 + i;
        red[s * 16 + tx]        = accP[i];
        red[1024 + s * 16 + tx] = accV[i];
    }
    __syncthreads();

    if (t < 64) {
        float rPr = 0.0f, tq = 0.0f;
        #pragma unroll
        for (int j = 0; j < 16; j++) {
            rPr += red[t * 16 + j];
            tq  += red[1024 + t * 16 + j];
        }
        float cst = g_cst[c];
        float d4  = tq * tq - rPr * (2.0f * cst);
        float aq  = (-tq + sqrtf(d4)) / rPr;
        float al  = -cst / tq;
        float mu  = (fabsf(rPr) <= 1e-12f) ? al : aq;
        // mu_pos: mu>=0 ? mu : inf  (NaN -> inf, matching jnp.where semantics)
        unsigned bits = (mu >= 0.0f) ? __float_as_uint(mu) : 0x7f800000u;
        atomicMin(&g_mu[s0 + t], bits);
    }
}

// ---------------- kernel 3: final projection --------------------------------
__global__ void k_final(const float* __restrict__ point,
                        float* __restrict__ out)
{
    int idx = blockIdx.x * 256 + threadIdx.x;
    int s = idx >> 8;
    int f = idx & 255;
    float maxlen = __uint_as_float(g_mu[s]);
    float ls = fminf(g_len[s], maxlen);
    out[idx] = point[f] + ls * g_norm[idx];
}

// ---------------- launch ----------------------------------------------------
extern "C" void kernel_launch(void* const* d_in, const int* in_sizes, int n_in,
                              void* d_out, int out_size)
{
    const float* zs = (const float*)d_in[0];
    const float* P  = (const float*)d_in[1];
    const float* q  = (const float*)d_in[2];
    const float* b  = (const float*)d_in[3];
    const float* pt = (const float*)d_in[4];
    float* out = (float*)d_out;

    k_norm<<<S_TOT / 8, 256>>>(zs, pt);
    k_pre <<<C_TOT, 256>>>(P, q, b, pt);

    int smem_bytes = (256 * SBP + 32 * 64 + 256 + 2048) * (int)sizeof(float);
    cudaFuncSetAttribute(k_main, cudaFuncAttributeMaxDynamicSharedMemorySize,
                         smem_bytes);
    k_main<<<dim3(S_TOT / 64, C_TOT), 256, smem_bytes>>>(P);

    k_final<<<(S_TOT * F_TOT) / 256, 256>>>(pt, out);
}

// round 4
// speedup vs baseline: 2.3682x; 2.3682x over previous
#include <cuda_runtime.h>
#include <cuda_bf16.h>
#include <math.h>
#include <stdint.h>

// Problem shape (fixed by the dataset)
#define S_TOT 4096
#define C_TOT 64
#define F_TOT 256

// ---------------- scratch (device globals: no allocation allowed) ----------
__device__ float         g_norm[S_TOT * F_TOT];   // normalized rays r[s][f] (fp32)
__device__ float         g_len [S_TOT];           // ray lengths
__device__ unsigned      g_mu  [S_TOT];           // min over c of mu_pos (float bits)
__device__ float         g_v   [C_TOT * F_TOT];   // v_c = P_c t + q_c
__device__ float         g_cst [C_TOT];           // q.t + 0.5 tPt - b
__device__ __nv_bfloat16 g_Rhi [S_TOT * F_TOT];
__device__ __nv_bfloat16 g_Rlo [S_TOT * F_TOT];
__device__ __nv_bfloat16 g_Phi [C_TOT * F_TOT * F_TOT];
__device__ __nv_bfloat16 g_Plo [C_TOT * F_TOT * F_TOT];

// ---------------- PTX helpers (sm_80-era only: valid on plain sm_100) -------
__device__ __forceinline__ uint32_t smem_u32(const void* p) {
    uint32_t a;
    asm("{ .reg .u64 t; cvta.to.shared.u64 t, %1; cvt.u32.u64 %0, t; }"
        : "=r"(a) : "l"(p));
    return a;
}

__device__ __forceinline__ void ldsm_x4(uint32_t* r, uint32_t addr) {
    asm volatile("ldmatrix.sync.aligned.m8n8.x4.shared.b16 {%0,%1,%2,%3}, [%4];"
        : "=r"(r[0]), "=r"(r[1]), "=r"(r[2]), "=r"(r[3]) : "r"(addr));
}
__device__ __forceinline__ void ldsm_x2(uint32_t* r, uint32_t addr) {
    asm volatile("ldmatrix.sync.aligned.m8n8.x2.shared.b16 {%0,%1}, [%2];"
        : "=r"(r[0]), "=r"(r[1]) : "r"(addr));
}
__device__ __forceinline__ void mma16816(float* d, const uint32_t* a, const uint32_t* b) {
    asm volatile(
        "mma.sync.aligned.m16n8k16.row.col.f32.bf16.bf16.f32 "
        "{%0,%1,%2,%3}, {%4,%5,%6,%7}, {%8,%9}, {%0,%1,%2,%3};"
        : "+f"(d[0]), "+f"(d[1]), "+f"(d[2]), "+f"(d[3])
        : "r"(a[0]), "r"(a[1]), "r"(a[2]), "r"(a[3]), "r"(b[0]), "r"(b[1]));
}

#define CP_ASYNC16(dst, src) \
    asm volatile("cp.async.cg.shared.global [%0], [%1], 16;" \
                 :: "r"(dst), "l"(src) : "memory")

// ---------------- kernel 1: normalize rays, init mu, emit bf16 hi/lo -------
__global__ void k_norm(const float* __restrict__ zs,
                       const float* __restrict__ point)
{
    int warp = threadIdx.x >> 5;
    int lane = threadIdx.x & 31;
    int s = blockIdx.x * 8 + warp;

    const float4* z4 = (const float4*)(zs + (size_t)s * F_TOT);
    const float4* p4 = (const float4*)point;

    float4 a = z4[lane];
    float4 b = z4[lane + 32];
    float4 pa = p4[lane];
    float4 pb = p4[lane + 32];

    a.x -= pa.x; a.y -= pa.y; a.z -= pa.z; a.w -= pa.w;
    b.x -= pb.x; b.y -= pb.y; b.z -= pb.z; b.w -= pb.w;

    float ss = a.x*a.x + a.y*a.y + a.z*a.z + a.w*a.w
             + b.x*b.x + b.y*b.y + b.z*b.z + b.w*b.w;
    #pragma unroll
    for (int off = 16; off; off >>= 1)
        ss += __shfl_xor_sync(0xffffffffu, ss, off);

    float len = fmaxf(sqrtf(ss), 1e-12f);
    float inv = 1.0f / len;
    a.x *= inv; a.y *= inv; a.z *= inv; a.w *= inv;
    b.x *= inv; b.y *= inv; b.z *= inv; b.w *= inv;

    float4* o4 = (float4*)(g_norm + (size_t)s * F_TOT);
    o4[lane]      = a;
    o4[lane + 32] = b;

    // bf16 hi/lo split
    __nv_bfloat162* h2 = (__nv_bfloat162*)(g_Rhi + (size_t)s * F_TOT);
    __nv_bfloat162* l2 = (__nv_bfloat162*)(g_Rlo + (size_t)s * F_TOT);
    float v[8] = {a.x, a.y, a.z, a.w, b.x, b.y, b.z, b.w};
    int base2[2] = {2 * lane, 64 + 2 * lane};
    #pragma unroll
    for (int h = 0; h < 2; h++) {
        #pragma unroll
        for (int p = 0; p < 2; p++) {
            float x = v[h*4 + p*2], y = v[h*4 + p*2 + 1];
            __nv_bfloat16 hx = __float2bfloat16(x), hy = __float2bfloat16(y);
            __nv_bfloat16 lx = __float2bfloat16(x - __bfloat162float(hx));
            __nv_bfloat16 ly = __float2bfloat16(y - __bfloat162float(hy));
            h2[base2[h] + p] = __halves2bfloat162(hx, hy);
            l2[base2[h] + p] = __halves2bfloat162(lx, ly);
        }
    }

    if (lane == 0) {
        g_len[s] = len;
        g_mu[s]  = 0x7f800000u;   // +inf
    }
}

// ---------------- kernel: split P into bf16 hi/lo ---------------------------
__global__ void k_cvtP(const float* __restrict__ P)
{
    size_t i = (size_t)blockIdx.x * 256 + threadIdx.x;  // float4 index
    float4 x = ((const float4*)P)[i];
    __nv_bfloat16 h0 = __float2bfloat16(x.x), h1 = __float2bfloat16(x.y);
    __nv_bfloat16 h2 = __float2bfloat16(x.z), h3 = __float2bfloat16(x.w);
    __nv_bfloat16 l0 = __float2bfloat16(x.x - __bfloat162float(h0));
    __nv_bfloat16 l1 = __float2bfloat16(x.y - __bfloat162float(h1));
    __nv_bfloat16 l2 = __float2bfloat16(x.z - __bfloat162float(h2));
    __nv_bfloat16 l3 = __float2bfloat16(x.w - __bfloat162float(h3));
    ((__nv_bfloat162*)g_Phi)[2*i]   = __halves2bfloat162(h0, h1);
    ((__nv_bfloat162*)g_Phi)[2*i+1] = __halves2bfloat162(h2, h3);
    ((__nv_bfloat162*)g_Plo)[2*i]   = __halves2bfloat162(l0, l1);
    ((__nv_bfloat162*)g_Plo)[2*i+1] = __halves2bfloat162(l2, l3);
}

// ---------------- kernel: per-constraint precompute --------------------------
__global__ void k_pre(const float* __restrict__ P,
                      const float* __restrict__ q,
                      const float* __restrict__ b,
                      const float* __restrict__ point)
{
    int c = blockIdx.x;
    int k = threadIdx.x;

    __shared__ float t_sm[F_TOT];
    __shared__ float red1[F_TOT];
    __shared__ float red2[F_TOT];

    t_sm[k] = point[k];
    __syncthreads();

    const float* Pc = P + (size_t)c * F_TOT * F_TOT;
    float v = 0.0f;
    for (int f = 0; f < F_TOT; f++)
        v += Pc[f * F_TOT + k] * t_sm[f];

    float qk = q[c * F_TOT + k];
    float tk = t_sm[k];
    red1[k] = v  * tk;
    red2[k] = qk * tk;
    __syncthreads();
    for (int off = 128; off; off >>= 1) {
        if (k < off) { red1[k] += red1[k + off]; red2[k] += red2[k + off]; }
        __syncthreads();
    }
    g_v[c * F_TOT + k] = v + qk;
    if (k == 0)
        g_cst[c] = red2[0] + 0.5f * red1[0] - b[c];
}

// ---------------- main mma.sync kernel ---------------------------------------
// Grid (32, 64): 128-sample tile x constraint. 512 threads = 16 warps (4x4).
// Warp tile 32(s) x 64(f). acc[2 mtile][8 ntile][4] fp32 per thread.
// K concatenation: 12 chunks of K=64:
//   pass0 (chunks 0-3):  A=Rhi, B=Phi
//   pass1 (chunks 4-7):  A=Rhi, B=Plo
//   pass2 (chunks 8-11): A=Rlo, B=Phi
// SMEM (dynamic): v_c @0 (1KB), red @1024 (2KB),
//                 A stages @3072 (2x16KB), B stages @35840 (2x32KB)
#define OFF_V   0
#define OFF_RED 1024
#define OFF_A   3072
#define OFF_B   35840
#define SMEM_MMA 101376

__global__ void __launch_bounds__(512, 1) k_mma()
{
    extern __shared__ __align__(1024) char smem[];
    uint32_t sb = smem_u32(smem);
    int tid = threadIdx.x;
    int l   = tid & 31;
    int w   = tid >> 5;
    int wm  = w & 3;        // sample-tile row group (32 rows)
    int wn  = w >> 2;       // f-tile col group (64 cols)
    int s0  = blockIdx.x * 128;
    int c   = blockIdx.y;

    if (tid < 64)
        ((float4*)(smem + OFF_V))[tid] = ((const float4*)(g_v + c * F_TOT))[tid];

    auto issue_chunk = [&](int i) {
        int pass = i >> 2;
        int k0   = (i & 3) * 64;
        const __nv_bfloat16* Asrc = (pass < 2)  ? g_Rhi : g_Rlo;
        const __nv_bfloat16* Bsrc = (pass == 1) ? g_Plo : g_Phi;
        uint32_t ab = sb + OFF_A + (i & 1) * 16384;
        uint32_t bb = sb + OFF_B + (i & 1) * 32768;
        #pragma unroll
        for (int it = 0; it < 2; it++) {        // A: 128 rows x 8 x 16B
            int idx = it * 512 + tid;
            int row = idx >> 3, u = idx & 7;
            const char* src = (const char*)(Asrc + (size_t)(s0 + row) * F_TOT + k0 + u * 8);
            CP_ASYNC16(ab + row * 128 + (((u ^ (row & 7))) << 4), src);
        }
        #pragma unroll
        for (int it = 0; it < 4; it++) {        // B: 256 rows x 8 x 16B
            int idx = it * 512 + tid;
            int row = idx >> 3, u = idx & 7;
            const char* src = (const char*)(Bsrc + ((size_t)c * F_TOT + row) * F_TOT + k0 + u * 8);
            CP_ASYNC16(bb + row * 128 + (((u ^ (row & 7))) << 4), src);
        }
        asm volatile("cp.async.commit_group;" ::: "memory");
    };

    issue_chunk(0);
    issue_chunk(1);

    float acc[2][8][4];
    #pragma unroll
    for (int mt = 0; mt < 2; mt++)
        #pragma unroll
        for (int nt = 0; nt < 8; nt++)
            #pragma unroll
            for (int j = 0; j < 4; j++)
                acc[mt][nt][j] = 0.0f;

    // lane-invariant ldmatrix addressing pieces
    int xr   = l & 7;               // row&7 for both A and B rows this lane touches
    int uq   = (l >> 4) & 1;        // A: matrices 2,3 use k-unit +1
    int aq   = (l >> 3) & 1;        // A: matrices 1,3 use rows +8
    int lb   = l & 15;
    int hB   = (lb >> 3) & 1;       // B: matrix 1 uses k-unit +1
    int rowB = wn * 64 + (lb & 7);
    int xrB  = lb & 7;

    for (int i = 0; i < 12; i++) {
        if (i < 11) asm volatile("cp.async.wait_group 1;" ::: "memory");
        else        asm volatile("cp.async.wait_group 0;" ::: "memory");
        __syncthreads();

        uint32_t ab = sb + OFF_A + (i & 1) * 16384;
        uint32_t bb = sb + OFF_B + (i & 1) * 32768;
        uint32_t aAddr0 = ab + (wm * 32 + aq * 8 + xr) * 128;   // mt=0 rows
        uint32_t aAddr1 = aAddr0 + 16 * 128;                    // mt=1 rows
        uint32_t bAddr  = bb + rowB * 128;

        #pragma unroll
        for (int ks = 0; ks < 4; ks++) {
            int u0 = ks * 2;
            uint32_t swzA = ((uint32_t)((u0 + uq) ^ xr))  << 4;
            uint32_t swzB = ((uint32_t)((u0 + hB) ^ xrB)) << 4;
            uint32_t afr[2][4];
            ldsm_x4(afr[0], aAddr0 + swzA);
            ldsm_x4(afr[1], aAddr1 + swzA);
            #pragma unroll
            for (int nt = 0; nt < 8; nt++) {
                uint32_t bfr[2];
                ldsm_x2(bfr, bAddr + nt * 1024 + swzB);
                mma16816(acc[0][nt], afr[0], bfr);
                mma16816(acc[1][nt], afr[1], bfr);
            }
        }
        __syncthreads();
        if (i + 2 < 12) issue_chunk(i + 2);
    }

    // ---- epilogue: rPr[s] = sum_f U[s][f] * r[s][f] --------------------------
    // acc layout (m16n8): d0,d1 -> row l/4, cols (l%4)*2 +{0,1}; d2,d3 -> row+8
    float part[4];
    #pragma unroll
    for (int mt = 0; mt < 2; mt++) {
        #pragma unroll
        for (int half = 0; half < 2; half++) {
            int row = wm * 32 + mt * 16 + (l >> 2) + half * 8;
            const float* rrow = g_norm + (size_t)(s0 + row) * F_TOT;
            float p = 0.0f;
            #pragma unroll
            for (int nt = 0; nt < 8; nt++) {
                int f = wn * 64 + nt * 8 + (l & 3) * 2;
                float2 rv = *(const float2*)(rrow + f);
                p += acc[mt][nt][half * 2 + 0] * rv.x
                   + acc[mt][nt][half * 2 + 1] * rv.y;
            }
            part[mt * 2 + half] = p;
        }
    }
    #pragma unroll
    for (int j = 0; j < 4; j++) {
        part[j] += __shfl_xor_sync(0xffffffffu, part[j], 1);
        part[j] += __shfl_xor_sync(0xffffffffu, part[j], 2);
    }
    float* red = (float*)(smem + OFF_RED);
    if ((l & 3) == 0) {
        #pragma unroll
        for (int j = 0; j < 4; j++) {
            int row = wm * 32 + (j >> 1) * 16 + (l >> 2) + (j & 1) * 8;
            red[row * 4 + wn] = part[j];
        }
    }
    __syncthreads();

    if (tid < 128) {
        float rPr = red[tid * 4 + 0] + red[tid * 4 + 1]
                  + red[tid * 4 + 2] + red[tid * 4 + 3];
        // tq = r . v_c  (fp32)
        const float4* rr = (const float4*)(g_norm + (size_t)(s0 + tid) * F_TOT);
        const float4* vv = (const float4*)(smem + OFF_V);
        float tq = 0.0f;
        #pragma unroll 8
        for (int g4 = 0; g4 < 64; g4++) {
            float4 a = rr[g4], bq = vv[g4];
            tq += a.x * bq.x + a.y * bq.y + a.z * bq.z + a.w * bq.w;
        }
        float cst = g_cst[c];
        float d4  = tq * tq - rPr * (2.0f * cst);
        float aqv = (-tq + sqrtf(d4)) / rPr;
        float al  = -cst / tq;
        float mu  = (fabsf(rPr) <= 1e-12f) ? al : aqv;
        unsigned bits = (mu >= 0.0f) ? __float_as_uint(mu) : 0x7f800000u;
        atomicMin(&g_mu[s0 + tid], bits);
    }
}

// ---------------- final projection ------------------------------------------
__global__ void k_final(const float* __restrict__ point,
                        float* __restrict__ out)
{
    int idx = blockIdx.x * 256 + threadIdx.x;
    int s = idx >> 8;
    int f = idx & 255;
    float maxlen = __uint_as_float(g_mu[s]);
    float ls = fminf(g_len[s], maxlen);
    out[idx] = point[f] + ls * g_norm[idx];
}

// ---------------- launch ----------------------------------------------------
extern "C" void kernel_launch(void* const* d_in, const int* in_sizes, int n_in,
                              void* d_out, int out_size)
{
    const float* zs = (const float*)d_in[0];
    const float* P  = (const float*)d_in[1];
    const float* q  = (const float*)d_in[2];
    const float* b  = (const float*)d_in[3];
    const float* pt = (const float*)d_in[4];
    float* out = (float*)d_out;

    k_norm<<<S_TOT / 8, 256>>>(zs, pt);
    k_cvtP<<<(C_TOT * F_TOT * F_TOT) / 4 / 256, 256>>>(P);
    k_pre <<<C_TOT, 256>>>(P, q, b, pt);

    cudaFuncSetAttribute(k_mma, cudaFuncAttributeMaxDynamicSharedMemorySize,
                         SMEM_MMA);
    k_mma<<<dim3(S_TOT / 128, C_TOT), 512, SMEM_MMA>>>();

    k_final<<<(S_TOT * F_TOT) / 256, 256>>>(pt, out);
}

// round 5
// speedup vs baseline: 3.0482x; 1.2871x over previous
#include <cuda_runtime.h>
#include <cuda_bf16.h>
#include <math.h>
#include <stdint.h>

// Problem shape (fixed by the dataset)
#define S_TOT 4096
#define C_TOT 64
#define F_TOT 256

// ---------------- scratch (device globals: no allocation allowed) ----------
__device__ float         g_norm[S_TOT * F_TOT];   // normalized rays r[s][f] (fp32)
__device__ float         g_len [S_TOT];           // ray lengths
__device__ unsigned      g_mu  [S_TOT];           // min over c of mu_pos (float bits)
__device__ float         g_v   [C_TOT * F_TOT];   // v_c = P_c t + q_c
__device__ float         g_cst [C_TOT];           // q.t + 0.5 tPt - b
__device__ __nv_bfloat16 g_Rhi [S_TOT * F_TOT];
__device__ __nv_bfloat16 g_Phi [C_TOT * F_TOT * F_TOT];
__device__ __nv_bfloat16 g_Plo [C_TOT * F_TOT * F_TOT];

// ---------------- PTX helpers (sm_80-era only: valid on plain sm_100) -------
__device__ __forceinline__ uint32_t smem_u32(const void* p) {
    uint32_t a;
    asm("{ .reg .u64 t; cvta.to.shared.u64 t, %1; cvt.u32.u64 %0, t; }"
        : "=r"(a) : "l"(p));
    return a;
}

__device__ __forceinline__ void ldsm_x4(uint32_t* r, uint32_t addr) {
    asm volatile("ldmatrix.sync.aligned.m8n8.x4.shared.b16 {%0,%1,%2,%3}, [%4];"
        : "=r"(r[0]), "=r"(r[1]), "=r"(r[2]), "=r"(r[3]) : "r"(addr));
}
__device__ __forceinline__ void mma16816(float* d, const uint32_t* a, const uint32_t* b) {
    asm volatile(
        "mma.sync.aligned.m16n8k16.row.col.f32.bf16.bf16.f32 "
        "{%0,%1,%2,%3}, {%4,%5,%6,%7}, {%8,%9}, {%0,%1,%2,%3};"
        : "+f"(d[0]), "+f"(d[1]), "+f"(d[2]), "+f"(d[3])
        : "r"(a[0]), "r"(a[1]), "r"(a[2]), "r"(a[3]), "r"(b[0]), "r"(b[1]));
}

#define CP_ASYNC16(dst, src) \
    asm volatile("cp.async.cg.shared.global [%0], [%1], 16;" \
                 :: "r"(dst), "l"(src) : "memory")

// ---------------- kernel 1: normalize rays, init mu, emit bf16 hi ----------
__global__ void k_norm(const float* __restrict__ zs,
                       const float* __restrict__ point)
{
    int warp = threadIdx.x >> 5;
    int lane = threadIdx.x & 31;
    int s = blockIdx.x * 8 + warp;

    const float4* z4 = (const float4*)(zs + (size_t)s * F_TOT);
    const float4* p4 = (const float4*)point;

    float4 a = z4[lane];
    float4 b = z4[lane + 32];
    float4 pa = p4[lane];
    float4 pb = p4[lane + 32];

    a.x -= pa.x; a.y -= pa.y; a.z -= pa.z; a.w -= pa.w;
    b.x -= pb.x; b.y -= pb.y; b.z -= pb.z; b.w -= pb.w;

    float ss = a.x*a.x + a.y*a.y + a.z*a.z + a.w*a.w
             + b.x*b.x + b.y*b.y + b.z*b.z + b.w*b.w;
    #pragma unroll
    for (int off = 16; off; off >>= 1)
        ss += __shfl_xor_sync(0xffffffffu, ss, off);

    float len = fmaxf(sqrtf(ss), 1e-12f);
    float inv = 1.0f / len;
    a.x *= inv; a.y *= inv; a.z *= inv; a.w *= inv;
    b.x *= inv; b.y *= inv; b.z *= inv; b.w *= inv;

    float4* o4 = (float4*)(g_norm + (size_t)s * F_TOT);
    o4[lane]      = a;
    o4[lane + 32] = b;

    __nv_bfloat162* h2 = (__nv_bfloat162*)(g_Rhi + (size_t)s * F_TOT);
    float v[8] = {a.x, a.y, a.z, a.w, b.x, b.y, b.z, b.w};
    int base2[2] = {2 * lane, 64 + 2 * lane};
    #pragma unroll
    for (int h = 0; h < 2; h++) {
        #pragma unroll
        for (int p = 0; p < 2; p++) {
            float x = v[h*4 + p*2], y = v[h*4 + p*2 + 1];
            h2[base2[h] + p] =
                __halves2bfloat162(__float2bfloat16(x), __float2bfloat16(y));
        }
    }

    if (lane == 0) {
        g_len[s] = len;
        g_mu[s]  = 0x7f800000u;   // +inf
    }
}

// ---------------- kernel: split P into bf16 hi/lo ---------------------------
__global__ void k_cvtP(const float* __restrict__ P)
{
    size_t i = (size_t)blockIdx.x * 256 + threadIdx.x;  // float4 index
    float4 x = ((const float4*)P)[i];
    __nv_bfloat16 h0 = __float2bfloat16(x.x), h1 = __float2bfloat16(x.y);
    __nv_bfloat16 h2 = __float2bfloat16(x.z), h3 = __float2bfloat16(x.w);
    __nv_bfloat16 l0 = __float2bfloat16(x.x - __bfloat162float(h0));
    __nv_bfloat16 l1 = __float2bfloat16(x.y - __bfloat162float(h1));
    __nv_bfloat16 l2 = __float2bfloat16(x.z - __bfloat162float(h2));
    __nv_bfloat16 l3 = __float2bfloat16(x.w - __bfloat162float(h3));
    ((__nv_bfloat162*)g_Phi)[2*i]   = __halves2bfloat162(h0, h1);
    ((__nv_bfloat162*)g_Phi)[2*i+1] = __halves2bfloat162(h2, h3);
    ((__nv_bfloat162*)g_Plo)[2*i]   = __halves2bfloat162(l0, l1);
    ((__nv_bfloat162*)g_Plo)[2*i+1] = __halves2bfloat162(l2, l3);
}

// ---------------- kernel: per-constraint precompute --------------------------
__global__ void k_pre(const float* __restrict__ P,
                      const float* __restrict__ q,
                      const float* __restrict__ b,
                      const float* __restrict__ point)
{
    int c = blockIdx.x;
    int k = threadIdx.x;

    __shared__ float t_sm[F_TOT];
    __shared__ float red1[F_TOT];
    __shared__ float red2[F_TOT];

    t_sm[k] = point[k];
    __syncthreads();

    const float* Pc = P + (size_t)c * F_TOT * F_TOT;
    float v = 0.0f;
    for (int f = 0; f < F_TOT; f++)
        v += Pc[f * F_TOT + k] * t_sm[f];

    float qk = q[c * F_TOT + k];
    float tk = t_sm[k];
    red1[k] = v  * tk;
    red2[k] = qk * tk;
    __syncthreads();
    for (int off = 128; off; off >>= 1) {
        if (k < off) { red1[k] += red1[k + off]; red2[k] += red2[k + off]; }
        __syncthreads();
    }
    g_v[c * F_TOT + k] = v + qk;
    if (k == 0)
        g_cst[c] = red2[0] + 0.5f * red1[0] - b[c];
}

// ---------------- main mma.sync kernel ---------------------------------------
// Grid (32, 64): 128-sample tile x constraint. 512 threads = 16 warps, 2(m)x8(n).
// Warp tile 64(s) x 32(f). acc[4 mtile][4 ntile][4] fp32.
// Single accumulation: W = Rhi . (Phi || Plo), 8 K=64 chunks:
//   chunk i: pair = i>>1, k0 = pair*64, B = (i&1) ? Plo : Phi
//   A (Rhi, per pair) loaded on even chunks only.
// Epilogue: rPr = sum_f W[s,f] * (2*r - rhi)[s,f]   (symmetric-P identity)
// SMEM: v_c @0 (1KB), red @1024 (4KB), A @5120 (2x16KB), B @37888 (2x32KB)
#define OFF_V   0
#define OFF_RED 1024
#define OFF_A   5120
#define OFF_B   37888
#define SMEM_MMA 103424

__global__ void __launch_bounds__(512, 1) k_mma()
{
    extern __shared__ __align__(1024) char smem[];
    uint32_t sb = smem_u32(smem);
    int tid = threadIdx.x;
    int l   = tid & 31;
    int w   = tid >> 5;
    int wm  = w & 1;        // sample group (64 rows)
    int wn  = w >> 1;       // f group (32 cols)
    int s0  = blockIdx.x * 128;
    int c   = blockIdx.y;

    if (tid < 64)
        ((float4*)(smem + OFF_V))[tid] = ((const float4*)(g_v + c * F_TOT))[tid];

    auto issue_chunk = [&](int i) {
        int pair = i >> 1;
        int k0   = pair * 64;
        if (!(i & 1)) {  // A: Rhi pair tile, 128 rows x 8 x 16B
            uint32_t ab = sb + OFF_A + (pair & 1) * 16384;
            #pragma unroll
            for (int it = 0; it < 2; it++) {
                int idx = it * 512 + tid;
                int row = idx >> 3, u = idx & 7;
                const char* src = (const char*)(g_Rhi + (size_t)(s0 + row) * F_TOT + k0 + u * 8);
                CP_ASYNC16(ab + row * 128 + (((u ^ (row & 7))) << 4), src);
            }
        }
        const __nv_bfloat16* Bsrc = (i & 1) ? g_Plo : g_Phi;
        uint32_t bb = sb + OFF_B + (i & 1) * 32768;
        #pragma unroll
        for (int it = 0; it < 4; it++) {        // B: 256 rows x 8 x 16B
            int idx = it * 512 + tid;
            int row = idx >> 3, u = idx & 7;
            const char* src = (const char*)(Bsrc + ((size_t)c * F_TOT + row) * F_TOT + k0 + u * 8);
            CP_ASYNC16(bb + row * 128 + (((u ^ (row & 7))) << 4), src);
        }
        asm volatile("cp.async.commit_group;" ::: "memory");
    };

    issue_chunk(0);
    issue_chunk(1);

    float acc[4][4][4];
    #pragma unroll
    for (int mt = 0; mt < 4; mt++)
        #pragma unroll
        for (int nt = 0; nt < 4; nt++)
            #pragma unroll
            for (int j = 0; j < 4; j++)
                acc[mt][nt][j] = 0.0f;

    // lane-invariant ldmatrix addressing
    int xr = l & 7;             // row & 7
    int aq = (l >> 3) & 1;      // A x4: matrices 1,3 rows +8
    int uq = (l >> 4) & 1;      // A x4: matrices 2,3 k-unit +1
    int ub = (l >> 3) & 1;      // B x4: matrices 1,3 k-unit +1
    int bg = (l >> 4) & 1;      // B x4: matrices 2,3 rows +8 (next n-tile)

    for (int i = 0; i < 8; i++) {
        if (i < 7) asm volatile("cp.async.wait_group 1;" ::: "memory");
        else       asm volatile("cp.async.wait_group 0;" ::: "memory");
        __syncthreads();

        uint32_t ab = sb + OFF_A + ((i >> 1) & 1) * 16384;
        uint32_t bb = sb + OFF_B + (i & 1) * 32768;
        uint32_t aAddr = ab + (wm * 64 + aq * 8 + xr) * 128;   // + mt*16*128
        uint32_t bAddr = bb + (wn * 32 + bg * 8 + xr) * 128;   // + p*16*128

        #pragma unroll
        for (int ks = 0; ks < 4; ks++) {
            int u0 = ks * 2;
            uint32_t swzA = ((uint32_t)((u0 + uq) ^ xr)) << 4;
            uint32_t swzB = ((uint32_t)((u0 + ub) ^ xr)) << 4;
            uint32_t afr[4][4];
            #pragma unroll
            for (int mt = 0; mt < 4; mt++)
                ldsm_x4(afr[mt], aAddr + mt * 2048 + swzA);
            #pragma unroll
            for (int p = 0; p < 2; p++) {
                uint32_t bfr[4];                 // n-tiles 2p (r0,r1), 2p+1 (r2,r3)
                ldsm_x4(bfr, bAddr + p * 2048 + swzB);
                #pragma unroll
                for (int mt = 0; mt < 4; mt++) {
                    mma16816(acc[mt][2*p],     afr[mt], bfr);
                    mma16816(acc[mt][2*p + 1], afr[mt], bfr + 2);
                }
            }
        }
        __syncthreads();
        if (i + 2 < 8) issue_chunk(i + 2);
    }

    // ---- epilogue: rPr[s] = sum_f W[s,f] * (2r - rhi)[s,f] -------------------
    float part[8];
    #pragma unroll
    for (int mt = 0; mt < 4; mt++) {
        #pragma unroll
        for (int half = 0; half < 2; half++) {
            int row = wm * 64 + mt * 16 + (l >> 2) + half * 8;
            const float* rrow = g_norm + (size_t)(s0 + row) * F_TOT;
            float p = 0.0f;
            #pragma unroll
            for (int nt = 0; nt < 4; nt++) {
                int f = wn * 32 + nt * 8 + (l & 3) * 2;
                float2 rv = *(const float2*)(rrow + f);
                float wx = 2.0f * rv.x - __bfloat162float(__float2bfloat16(rv.x));
                float wy = 2.0f * rv.y - __bfloat162float(__float2bfloat16(rv.y));
                p += acc[mt][nt][half * 2 + 0] * wx
                   + acc[mt][nt][half * 2 + 1] * wy;
            }
            part[mt * 2 + half] = p;
        }
    }
    #pragma unroll
    for (int j = 0; j < 8; j++) {
        part[j] += __shfl_xor_sync(0xffffffffu, part[j], 1);
        part[j] += __shfl_xor_sync(0xffffffffu, part[j], 2);
    }
    float* red = (float*)(smem + OFF_RED);
    if ((l & 3) == 0) {
        #pragma unroll
        for (int j = 0; j < 8; j++) {
            int row = wm * 64 + (j >> 1) * 16 + (l >> 2) + (j & 1) * 8;
            red[row * 8 + wn] = part[j];
        }
    }
    __syncthreads();

    if (tid < 128) {
        float rPr = 0.0f;
        #pragma unroll
        for (int j = 0; j < 8; j++)
            rPr += red[tid * 8 + j];
        // tq = r . v_c  (fp32)
        const float4* rr = (const float4*)(g_norm + (size_t)(s0 + tid) * F_TOT);
        const float4* vv = (const float4*)(smem + OFF_V);
        float tq = 0.0f;
        #pragma unroll 8
        for (int g4 = 0; g4 < 64; g4++) {
            float4 a = rr[g4], bq = vv[g4];
            tq += a.x * bq.x + a.y * bq.y + a.z * bq.z + a.w * bq.w;
        }
        float cst = g_cst[c];
        float d4  = tq * tq - rPr * (2.0f * cst);
        float aqv = (-tq + sqrtf(d4)) / rPr;
        float al  = -cst / tq;
        float mu  = (fabsf(rPr) <= 1e-12f) ? al : aqv;
        unsigned bits = (mu >= 0.0f) ? __float_as_uint(mu) : 0x7f800000u;
        atomicMin(&g_mu[s0 + tid], bits);
    }
}

// ---------------- final projection ------------------------------------------
__global__ void k_final(const float* __restrict__ point,
                        float* __restrict__ out)
{
    int idx = blockIdx.x * 256 + threadIdx.x;
    int s = idx >> 8;
    int f = idx & 255;
    float maxlen = __uint_as_float(g_mu[s]);
    float ls = fminf(g_len[s], maxlen);
    out[idx] = point[f] + ls * g_norm[idx];
}

// ---------------- launch ----------------------------------------------------
extern "C" void kernel_launch(void* const* d_in, const int* in_sizes, int n_in,
                              void* d_out, int out_size)
{
    const float* zs = (const float*)d_in[0];
    const float* P  = (const float*)d_in[1];
    const float* q  = (const float*)d_in[2];
    const float* b  = (const float*)d_in[3];
    const float* pt = (const float*)d_in[4];
    float* out = (float*)d_out;

    k_norm<<<S_TOT / 8, 256>>>(zs, pt);
    k_cvtP<<<(C_TOT * F_TOT * F_TOT) / 4 / 256, 256>>>(P);
    k_pre <<<C_TOT, 256>>>(P, q, b, pt);

    cudaFuncSetAttribute(k_mma, cudaFuncAttributeMaxDynamicSharedMemorySize,
                         SMEM_MMA);
    k_mma<<<dim3(S_TOT / 128, C_TOT), 512, SMEM_MMA>>>();

    k_final<<<(S_TOT * F_TOT) / 256, 256>>>(pt, out);
}

// round 6
// speedup vs baseline: 3.4179x; 1.1213x over previous
#include <cuda_runtime.h>
#include <cuda_bf16.h>
#include <math.h>
#include <stdint.h>

// Problem shape (fixed by the dataset)
#define S_TOT 4096
#define C_TOT 64
#define F_TOT 256

// ---------------- scratch (device globals: no allocation allowed) ----------
__device__ float         g_norm[S_TOT * F_TOT];   // normalized rays r[s][f] (fp32)
__device__ float         g_len [S_TOT];           // ray lengths
__device__ unsigned      g_mu  [S_TOT];           // min over c of mu_pos (float bits)
__device__ float         g_v   [C_TOT * F_TOT];   // v_c = P_c t + q_c
__device__ float         g_cst [C_TOT];           // q.t + 0.5 tPt - b
__device__ __nv_bfloat16 g_Rhi [S_TOT * F_TOT];
__device__ __nv_bfloat16 g_Phi [C_TOT * F_TOT * F_TOT];
__device__ __nv_bfloat16 g_Plo [C_TOT * F_TOT * F_TOT];

// ---------------- PTX helpers (sm_80-era only: valid on plain sm_100) -------
__device__ __forceinline__ uint32_t smem_u32(const void* p) {
    uint32_t a;
    asm("{ .reg .u64 t; cvta.to.shared.u64 t, %1; cvt.u32.u64 %0, t; }"
        : "=r"(a) : "l"(p));
    return a;
}

__device__ __forceinline__ void ldsm_x4(uint32_t* r, uint32_t addr) {
    asm volatile("ldmatrix.sync.aligned.m8n8.x4.shared.b16 {%0,%1,%2,%3}, [%4];"
        : "=r"(r[0]), "=r"(r[1]), "=r"(r[2]), "=r"(r[3]) : "r"(addr));
}
__device__ __forceinline__ void mma16816(float* d, const uint32_t* a, const uint32_t* b) {
    asm volatile(
        "mma.sync.aligned.m16n8k16.row.col.f32.bf16.bf16.f32 "
        "{%0,%1,%2,%3}, {%4,%5,%6,%7}, {%8,%9}, {%0,%1,%2,%3};"
        : "+f"(d[0]), "+f"(d[1]), "+f"(d[2]), "+f"(d[3])
        : "r"(a[0]), "r"(a[1]), "r"(a[2]), "r"(a[3]), "r"(b[0]), "r"(b[1]));
}

#define CP_ASYNC16(dst, src) \
    asm volatile("cp.async.cg.shared.global [%0], [%1], 16;" \
                 :: "r"(dst), "l"(src) : "memory")

// ---------------- kernel 1: normalize rays, init mu, emit bf16 hi ----------
__global__ void k_norm(const float* __restrict__ zs,
                       const float* __restrict__ point)
{
    int warp = threadIdx.x >> 5;
    int lane = threadIdx.x & 31;
    int s = blockIdx.x * 8 + warp;

    const float4* z4 = (const float4*)(zs + (size_t)s * F_TOT);
    const float4* p4 = (const float4*)point;

    float4 a = z4[lane];
    float4 b = z4[lane + 32];
    float4 pa = p4[lane];
    float4 pb = p4[lane + 32];

    a.x -= pa.x; a.y -= pa.y; a.z -= pa.z; a.w -= pa.w;
    b.x -= pb.x; b.y -= pb.y; b.z -= pb.z; b.w -= pb.w;

    float ss = a.x*a.x + a.y*a.y + a.z*a.z + a.w*a.w
             + b.x*b.x + b.y*b.y + b.z*b.z + b.w*b.w;
    #pragma unroll
    for (int off = 16; off; off >>= 1)
        ss += __shfl_xor_sync(0xffffffffu, ss, off);

    float len = fmaxf(sqrtf(ss), 1e-12f);
    float inv = 1.0f / len;
    a.x *= inv; a.y *= inv; a.z *= inv; a.w *= inv;
    b.x *= inv; b.y *= inv; b.z *= inv; b.w *= inv;

    float4* o4 = (float4*)(g_norm + (size_t)s * F_TOT);
    o4[lane]      = a;
    o4[lane + 32] = b;

    __nv_bfloat162* h2 = (__nv_bfloat162*)(g_Rhi + (size_t)s * F_TOT);
    float v[8] = {a.x, a.y, a.z, a.w, b.x, b.y, b.z, b.w};
    int base2[2] = {2 * lane, 64 + 2 * lane};
    #pragma unroll
    for (int h = 0; h < 2; h++) {
        #pragma unroll
        for (int p = 0; p < 2; p++) {
            float x = v[h*4 + p*2], y = v[h*4 + p*2 + 1];
            h2[base2[h] + p] =
                __halves2bfloat162(__float2bfloat16(x), __float2bfloat16(y));
        }
    }

    if (lane == 0) {
        g_len[s] = len;
        g_mu[s]  = 0x7f800000u;   // +inf
    }
}

// ---------------- kernel: split P into bf16 hi/lo ---------------------------
__global__ void k_cvtP(const float* __restrict__ P)
{
    size_t i = (size_t)blockIdx.x * 256 + threadIdx.x;  // float4 index
    float4 x = ((const float4*)P)[i];
    __nv_bfloat16 h0 = __float2bfloat16(x.x), h1 = __float2bfloat16(x.y);
    __nv_bfloat16 h2 = __float2bfloat16(x.z), h3 = __float2bfloat16(x.w);
    __nv_bfloat16 l0 = __float2bfloat16(x.x - __bfloat162float(h0));
    __nv_bfloat16 l1 = __float2bfloat16(x.y - __bfloat162float(h1));
    __nv_bfloat16 l2 = __float2bfloat16(x.z - __bfloat162float(h2));
    __nv_bfloat16 l3 = __float2bfloat16(x.w - __bfloat162float(h3));
    ((__nv_bfloat162*)g_Phi)[2*i]   = __halves2bfloat162(h0, h1);
    ((__nv_bfloat162*)g_Phi)[2*i+1] = __halves2bfloat162(h2, h3);
    ((__nv_bfloat162*)g_Plo)[2*i]   = __halves2bfloat162(l0, l1);
    ((__nv_bfloat162*)g_Plo)[2*i+1] = __halves2bfloat162(l2, l3);
}

// ---------------- kernel: per-constraint precompute --------------------------
__global__ void k_pre(const float* __restrict__ P,
                      const float* __restrict__ q,
                      const float* __restrict__ b,
                      const float* __restrict__ point)
{
    int c = blockIdx.x;
    int k = threadIdx.x;

    __shared__ float t_sm[F_TOT];
    __shared__ float red1[F_TOT];
    __shared__ float red2[F_TOT];

    t_sm[k] = point[k];
    __syncthreads();

    const float* Pc = P + (size_t)c * F_TOT * F_TOT;
    float v = 0.0f;
    for (int f = 0; f < F_TOT; f++)
        v += Pc[f * F_TOT + k] * t_sm[f];

    float qk = q[c * F_TOT + k];
    float tk = t_sm[k];
    red1[k] = v  * tk;
    red2[k] = qk * tk;
    __syncthreads();
    for (int off = 128; off; off >>= 1) {
        if (k < off) { red1[k] += red1[k + off]; red2[k] += red2[k + off]; }
        __syncthreads();
    }
    g_v[c * F_TOT + k] = v + qk;
    if (k == 0)
        g_cst[c] = red2[0] + 0.5f * red1[0] - b[c];
}

// ---------------- main mma.sync kernel ---------------------------------------
// Grid (32, 64): 128-sample tile x constraint. 512 threads = 16 warps, 2(m)x8(n).
// Warp tile 64(s) x 32(f). acc[4 mtile][4 ntile][4] fp32.
// Single accumulation: W = Rhi . (Phi || Plo), 8 K=64 chunks:
//   chunk i: pair = i>>1, k0 = pair*64, B = (i&1) ? Plo : Phi
//   A (Rhi, per pair) loaded on even chunks only.
// Epilogue: rPr = sum_f W[s,f] * (2*r - rhi)[s,f]   (symmetric-P identity)
//
// Pipeline: 3-stage buffers (A by pair%3, B by chunk%3), ONE __syncthreads
// per chunk, cp.async for chunk i+2 issued right after the barrier so it
// overlaps the whole compute of chunk i. wait_group 1 at iter top => chunk i
// resident; barrier publishes it. Buffer (i+2)%3 is disjoint from b_i, b_{i+1},
// and its previous readers (iter i-1) are past the iter-i barrier => no WAR.
//
// SMEM: v_c @0 (1KB), red @1024 (4KB), A @5120 (3x16KB), B @54272 (3x32KB)
#define OFF_V   0
#define OFF_RED 1024
#define OFF_A   5120
#define OFF_B   54272
#define SMEM_MMA 152576

__global__ void __launch_bounds__(512, 1) k_mma()
{
    extern __shared__ __align__(1024) char smem[];
    uint32_t sb = smem_u32(smem);
    int tid = threadIdx.x;
    int l   = tid & 31;
    int w   = tid >> 5;
    int wm  = w & 1;        // sample group (64 rows)
    int wn  = w >> 1;       // f group (32 cols)
    int s0  = blockIdx.x * 128;
    int c   = blockIdx.y;

    if (tid < 64)
        ((float4*)(smem + OFF_V))[tid] = ((const float4*)(g_v + c * F_TOT))[tid];

    auto issue_chunk = [&](int i) {
        int pair = i >> 1;
        int k0   = pair * 64;
        if (!(i & 1)) {  // A: Rhi pair tile, 128 rows x 8 x 16B
            uint32_t ab = sb + OFF_A + (pair % 3) * 16384;
            #pragma unroll
            for (int it = 0; it < 2; it++) {
                int idx = it * 512 + tid;
                int row = idx >> 3, u = idx & 7;
                const char* src = (const char*)(g_Rhi + (size_t)(s0 + row) * F_TOT + k0 + u * 8);
                CP_ASYNC16(ab + row * 128 + (((u ^ (row & 7))) << 4), src);
            }
        }
        const __nv_bfloat16* Bsrc = (i & 1) ? g_Plo : g_Phi;
        uint32_t bb = sb + OFF_B + (i % 3) * 32768;
        #pragma unroll
        for (int it = 0; it < 4; it++) {        // B: 256 rows x 8 x 16B
            int idx = it * 512 + tid;
            int row = idx >> 3, u = idx & 7;
            const char* src = (const char*)(Bsrc + ((size_t)c * F_TOT + row) * F_TOT + k0 + u * 8);
            CP_ASYNC16(bb + row * 128 + (((u ^ (row & 7))) << 4), src);
        }
        asm volatile("cp.async.commit_group;" ::: "memory");
    };

    issue_chunk(0);
    issue_chunk(1);

    float acc[4][4][4];
    #pragma unroll
    for (int mt = 0; mt < 4; mt++)
        #pragma unroll
        for (int nt = 0; nt < 4; nt++)
            #pragma unroll
            for (int j = 0; j < 4; j++)
                acc[mt][nt][j] = 0.0f;

    // lane-invariant ldmatrix addressing
    int xr = l & 7;             // row & 7
    int aq = (l >> 3) & 1;      // A x4: matrices 1,3 rows +8
    int uq = (l >> 4) & 1;      // A x4: matrices 2,3 k-unit +1
    int ub = (l >> 3) & 1;      // B x4: matrices 1,3 k-unit +1
    int bg = (l >> 4) & 1;      // B x4: matrices 2,3 rows +8 (next n-tile)

    for (int i = 0; i < 8; i++) {
        if (i < 7) asm volatile("cp.async.wait_group 1;" ::: "memory");
        else       asm volatile("cp.async.wait_group 0;" ::: "memory");
        __syncthreads();
        if (i + 2 < 8) issue_chunk(i + 2);   // overlaps compute of chunk i

        uint32_t ab = sb + OFF_A + ((i >> 1) % 3) * 16384;
        uint32_t bb = sb + OFF_B + (i % 3) * 32768;
        uint32_t aAddr = ab + (wm * 64 + aq * 8 + xr) * 128;   // + mt*16*128
        uint32_t bAddr = bb + (wn * 32 + bg * 8 + xr) * 128;   // + p*16*128

        #pragma unroll
        for (int ks = 0; ks < 4; ks++) {
            int u0 = ks * 2;
            uint32_t swzA = ((uint32_t)((u0 + uq) ^ xr)) << 4;
            uint32_t swzB = ((uint32_t)((u0 + ub) ^ xr)) << 4;
            uint32_t afr[4][4];
            #pragma unroll
            for (int mt = 0; mt < 4; mt++)
                ldsm_x4(afr[mt], aAddr + mt * 2048 + swzA);
            #pragma unroll
            for (int p = 0; p < 2; p++) {
                uint32_t bfr[4];                 // n-tiles 2p (r0,r1), 2p+1 (r2,r3)
                ldsm_x4(bfr, bAddr + p * 2048 + swzB);
                #pragma unroll
                for (int mt = 0; mt < 4; mt++) {
                    mma16816(acc[mt][2*p],     afr[mt], bfr);
                    mma16816(acc[mt][2*p + 1], afr[mt], bfr + 2);
                }
            }
        }
    }

    // ---- epilogue: rPr[s] = sum_f W[s,f] * (2r - rhi)[s,f] -------------------
    float part[8];
    #pragma unroll
    for (int mt = 0; mt < 4; mt++) {
        #pragma unroll
        for (int half = 0; half < 2; half++) {
            int row = wm * 64 + mt * 16 + (l >> 2) + half * 8;
            const float* rrow = g_norm + (size_t)(s0 + row) * F_TOT;
            float p = 0.0f;
            #pragma unroll
            for (int nt = 0; nt < 4; nt++) {
                int f = wn * 32 + nt * 8 + (l & 3) * 2;
                float2 rv = *(const float2*)(rrow + f);
                float wx = 2.0f * rv.x - __bfloat162float(__float2bfloat16(rv.x));
                float wy = 2.0f * rv.y - __bfloat162float(__float2bfloat16(rv.y));
                p += acc[mt][nt][half * 2 + 0] * wx
                   + acc[mt][nt][half * 2 + 1] * wy;
            }
            part[mt * 2 + half] = p;
        }
    }
    #pragma unroll
    for (int j = 0; j < 8; j++) {
        part[j] += __shfl_xor_sync(0xffffffffu, part[j], 1);
        part[j] += __shfl_xor_sync(0xffffffffu, part[j], 2);
    }
    float* red = (float*)(smem + OFF_RED);
    __syncthreads();   // all reads of buffers done before red reuse is irrelevant; keeps ordering simple
    if ((l & 3) == 0) {
        #pragma unroll
        for (int j = 0; j < 8; j++) {
            int row = wm * 64 + (j >> 1) * 16 + (l >> 2) + (j & 1) * 8;
            red[row * 8 + wn] = part[j];
        }
    }
    __syncthreads();

    if (tid < 128) {
        float rPr = 0.0f;
        #pragma unroll
        for (int j = 0; j < 8; j++)
            rPr += red[tid * 8 + j];
        // tq = r . v_c  (fp32)
        const float4* rr = (const float4*)(g_norm + (size_t)(s0 + tid) * F_TOT);
        const float4* vv = (const float4*)(smem + OFF_V);
        float tq = 0.0f;
        #pragma unroll 8
        for (int g4 = 0; g4 < 64; g4++) {
            float4 a = rr[g4], bq = vv[g4];
            tq += a.x * bq.x + a.y * bq.y + a.z * bq.z + a.w * bq.w;
        }
        float cst = g_cst[c];
        float d4  = tq * tq - rPr * (2.0f * cst);
        float aqv = (-tq + sqrtf(d4)) / rPr;
        float al  = -cst / tq;
        float mu  = (fabsf(rPr) <= 1e-12f) ? al : aqv;
        unsigned bits = (mu >= 0.0f) ? __float_as_uint(mu) : 0x7f800000u;
        atomicMin(&g_mu[s0 + tid], bits);
    }
}

// ---------------- final projection ------------------------------------------
__global__ void k_final(const float* __restrict__ point,
                        float* __restrict__ out)
{
    int idx = blockIdx.x * 256 + threadIdx.x;
    int s = idx >> 8;
    int f = idx & 255;
    float maxlen = __uint_as_float(g_mu[s]);
    float ls = fminf(g_len[s], maxlen);
    out[idx] = point[f] + ls * g_norm[idx];
}

// ---------------- launch ----------------------------------------------------
extern "C" void kernel_launch(void* const* d_in, const int* in_sizes, int n_in,
                              void* d_out, int out_size)
{
    const float* zs = (const float*)d_in[0];
    const float* P  = (const float*)d_in[1];
    const float* q  = (const float*)d_in[2];
    const float* b  = (const float*)d_in[3];
    const float* pt = (const float*)d_in[4];
    float* out = (float*)d_out;

    k_norm<<<S_TOT / 8, 256>>>(zs, pt);
    k_cvtP<<<(C_TOT * F_TOT * F_TOT) / 4 / 256, 256>>>(P);
    k_pre <<<C_TOT, 256>>>(P, q, b, pt);

    cudaFuncSetAttribute(k_mma, cudaFuncAttributeMaxDynamicSharedMemorySize,
                         SMEM_MMA);
    k_mma<<<dim3(S_TOT / 128, C_TOT), 512, SMEM_MMA>>>();

    k_final<<<(S_TOT * F_TOT) / 256, 256>>>(pt, out);
}